// round 1
// baseline (speedup 1.0000x reference)
#include <cuda_runtime.h>
#include <stdint.h>

// Problem constants (this problem: B=1024, N=1024, T1=20000, T2=60000)
#define N_SP      1024
#define STRIDE    1025                      // 1025 % 32 == 1 -> conflict-free lane-per-row LDS
#define MAX_TERMS 131072
#define C_SPLIT   8                         // column splits per row-group
#define COLS_PER_CTA  (N_SP / C_SPLIT)      // 128
#define COLS_PER_WARP (COLS_PER_CTA / 32)   // 4
#define SMEM_BYTES (32 * STRIDE * 4)        // 131200 B

// __device__ scratch (allocation-free per harness rules)
__device__ int   d_counts[N_SP];
__device__ int   d_offsets[N_SP + 1];
__device__ int   d_cursor[N_SP];
__device__ uint2 d_rec[MAX_TERMS];          // {rate_bits, (ia*4) | (ib*4)<<16}

// ---------------- prep: counting sort of terms by output species ----------------

__global__ void zeroK() { d_counts[threadIdx.x] = 0; }

__global__ void histK(const int* __restrict__ o1, const int* __restrict__ o2,
                      int T1, int T2) {
    int t = blockIdx.x * blockDim.x + threadIdx.x;
    if (t >= T1 + T2) return;
    int o = (t < T1) ? o1[t] : o2[t - T1];
    atomicAdd(&d_counts[o], 1);
}

__global__ void scanK() {    // 1 block, N_SP threads: Hillis-Steele inclusive scan
    __shared__ int tmp[N_SP];
    int t = threadIdx.x;
    int v = d_counts[t];
    tmp[t] = v;
    __syncthreads();
    for (int ofs = 1; ofs < N_SP; ofs <<= 1) {
        int add = (t >= ofs) ? tmp[t - ofs] : 0;
        __syncthreads();
        tmp[t] += add;
        __syncthreads();
    }
    d_offsets[t + 1] = tmp[t];       // exclusive offsets
    d_cursor[t]      = tmp[t] - v;   // scatter cursor = exclusive prefix
    if (t == 0) d_offsets[0] = 0;
}

__global__ void scatterK(const float* __restrict__ r1, const float* __restrict__ r2,
                         const float* __restrict__ dn,
                         const int* __restrict__ ir1,
                         const int* __restrict__ ir2a, const int* __restrict__ ir2b,
                         const int* __restrict__ io1, const int* __restrict__ io2,
                         int T1, int T2) {
    int t = blockIdx.x * blockDim.x + threadIdx.x;
    if (t >= T1 + T2) return;
    float rate; int ia, ib, o;
    if (t < T1) {               // 1st-order: y[ia] * 1.0 (constant slot at index N_SP)
        rate = r1[t]; ia = ir1[t]; ib = N_SP; o = io1[t];
    } else {                    // 2nd-order: den_norm folded into rate
        int u = t - T1;
        rate = r2[u] * dn[0]; ia = ir2a[u]; ib = ir2b[u]; o = io2[u];
    }
    int pos = atomicAdd(&d_cursor[o], 1);
    d_rec[pos] = make_uint2(__float_as_uint(rate),
                            (uint32_t)(ia * 4) | ((uint32_t)(ib * 4) << 16));
}

// ---------------- main: gather kernel ----------------
// CTA = (row-group of 32 batch rows) x (column partition of 128 species).
// Warp w handles COLS_PER_WARP columns; lane = batch row within the group.
// y_sh stride 1025 floats -> lane-indexed row access is bank-conflict-free.

__global__ __launch_bounds__(1024, 1)
void mainK(const float* __restrict__ y, float* __restrict__ out) {
    extern __shared__ float y_sh[];   // 32 * STRIDE floats
    int rg    = blockIdx.x / C_SPLIT;
    int cpart = blockIdx.x % C_SPLIT;
    int tid   = threadIdx.x;

    const float* yb = y + (size_t)rg * 32 * N_SP;
#pragma unroll
    for (int i = tid; i < 32 * N_SP; i += 1024) {
        int row = i >> 10, col = i & (N_SP - 1);
        y_sh[row * STRIDE + col] = yb[i];
    }
    if (tid < 32) y_sh[tid * STRIDE + N_SP] = 1.0f;   // constant-1 slot for 1st-order terms
    __syncthreads();

    int lane = tid & 31, w = tid >> 5;
    const char* rowp = (const char*)(y_sh + lane * STRIDE);
    int cbase = cpart * COLS_PER_CTA + w * COLS_PER_WARP;

#pragma unroll
    for (int cc = 0; cc < COLS_PER_WARP; ++cc) {
        int col = cbase + cc;
        int s = d_offsets[col];
        int e = d_offsets[col + 1];
        float acc0 = 0.f, acc1 = 0.f;
        int p = s;
        for (; p + 2 <= e; p += 2) {               // unroll-2, dual accumulators
            uint2 q0 = d_rec[p];
            uint2 q1 = d_rec[p + 1];
            float va0 = *(const float*)(rowp + (q0.y & 0xFFFFu));
            float vb0 = *(const float*)(rowp + (q0.y >> 16));
            float va1 = *(const float*)(rowp + (q1.y & 0xFFFFu));
            float vb1 = *(const float*)(rowp + (q1.y >> 16));
            acc0 = fmaf(__uint_as_float(q0.x) * va0, vb0, acc0);
            acc1 = fmaf(__uint_as_float(q1.x) * va1, vb1, acc1);
        }
        if (p < e) {
            uint2 q0 = d_rec[p];
            float va0 = *(const float*)(rowp + (q0.y & 0xFFFFu));
            float vb0 = *(const float*)(rowp + (q0.y >> 16));
            acc0 = fmaf(__uint_as_float(q0.x) * va0, vb0, acc0);
        }
        out[(size_t)(rg * 32 + lane) * N_SP + col] = acc0 + acc1;
    }
}

// ---------------- launch ----------------

extern "C" void kernel_launch(void* const* d_in, const int* in_sizes, int n_in,
                              void* d_out, int out_size) {
    // metadata order: t_in, y_in, rates_1st, rates_2nd, den_norm,
    //                 inds_r1, inds_r2a, inds_r2b, inds_out1, inds_out2
    const float* y    = (const float*)d_in[1];
    const float* r1   = (const float*)d_in[2];
    const float* r2   = (const float*)d_in[3];
    const float* dn   = (const float*)d_in[4];
    const int*   ir1  = (const int*)d_in[5];
    const int*   ir2a = (const int*)d_in[6];
    const int*   ir2b = (const int*)d_in[7];
    const int*   io1  = (const int*)d_in[8];
    const int*   io2  = (const int*)d_in[9];
    float*       out  = (float*)d_out;

    int T1 = in_sizes[2];
    int T2 = in_sizes[3];
    int T  = T1 + T2;
    int B  = in_sizes[1] / N_SP;

    cudaFuncSetAttribute(mainK, cudaFuncAttributeMaxDynamicSharedMemorySize, SMEM_BYTES);

    zeroK<<<1, N_SP>>>();
    histK<<<(T + 255) / 256, 256>>>(io1, io2, T1, T2);
    scanK<<<1, N_SP>>>();
    scatterK<<<(T + 255) / 256, 256>>>(r1, r2, dn, ir1, ir2a, ir2b, io1, io2, T1, T2);
    mainK<<<(B / 32) * C_SPLIT, 1024, SMEM_BYTES>>>(y, out);
}